// round 10
// baseline (speedup 1.0000x reference)
#include <cuda_runtime.h>
#include <cuda_bf16.h>

// Persistent device state; last block resets to 0 so every graph replay
// starts from the same state.
__device__ double       g_acc   = 0.0;
__device__ unsigned int g_count = 0u;

// 16 threads per row, 1 float4 per thread per iteration, 8 iterations split
// into 2 batches of 4 with explicitly front-batched loads (MLP ~8/thread).
// Block of 256 threads covers 128 rows. Chunks entirely beyond n[row] are
// never loaded (exact: they're masked to zero anyway).
__global__ __launch_bounds__(256) void mahal_fused_kernel(
    const float4* __restrict__ yt,
    const float4* __restrict__ yp,
    const float*  __restrict__ param,
    const int*    __restrict__ n,
    float*        __restrict__ out,
    int B)
{
    const float pm = __ldg(&param[0]);
    const float p  = 2.0f / (1.0f + __expf(-pm)) - 1.0f;
    const float coef2 = -2.0f * p / (1.0f + p * p);   // 2*coef

    const int lin = threadIdx.x & 15;                 // chunk-in-row, constant
    const int t0  = lin * 4;                          // first column of my chunk

    float acc = 0.0f;
    const int blockBase = blockIdx.x * (256 * 8);     // first float4 chunk of block

#pragma unroll
    for (int bat = 0; bat < 2; bat++) {
        int   nv[4];
        float4 a[4], b[4];

        // Phase 1: n loads (L2-resident, cheap) — needed for load predicates.
#pragma unroll
        for (int j = 0; j < 4; j++) {
            const int cid = blockBase + (bat * 4 + j) * 256 + threadIdx.x;
            nv[j] = __ldg(&n[cid >> 4]);
        }

        // Phase 2: front-batch all data loads (up to 8 LDG.128 in flight).
#pragma unroll
        for (int j = 0; j < 4; j++) {
            const int cid = blockBase + (bat * 4 + j) * 256 + threadIdx.x;
            a[j] = make_float4(0.f, 0.f, 0.f, 0.f);
            b[j] = make_float4(0.f, 0.f, 0.f, 0.f);
            if (t0 < nv[j]) {
                a[j] = __ldcs(&yt[cid]);
                b[j] = __ldcs(&yp[cid]);
            }
        }

        // Phase 3: compute.
#pragma unroll
        for (int j = 0; j < 4; j++) {
            const int v = nv[j];
            float d0 = 0.f, d1 = 0.f, d2 = 0.f, d3 = 0.f;
            if (t0 < v) {
                d0 = a[j].x - b[j].x;
                d1 = (t0 + 1 < v) ? (a[j].y - b[j].y) : 0.0f;
                d2 = (t0 + 2 < v) ? (a[j].z - b[j].z) : 0.0f;
                d3 = (t0 + 3 < v) ? (a[j].w - b[j].w) : 0.0f;
            }

            float sumsq = d0 * d0;
            sumsq = fmaf(d1, d1, sumsq);
            sumsq = fmaf(d2, d2, sumsq);
            sumsq = fmaf(d3, d3, sumsq);

            float sumadj = d0 * d1;
            sumadj = fmaf(d1, d2, sumadj);
            sumadj = fmaf(d2, d3, sumadj);

            // cross-chunk adjacent product: my d3 * right-neighbor's d0.
            // All lanes execute the shfl; lanes with lin==15 skip the fma.
            const float nd0 = __shfl_down_sync(0xffffffffu, d0, 1);
            if (lin < 15) sumadj = fmaf(d3, nd0, sumadj);

            const float partial = fmaf(coef2, sumadj, sumsq);
            acc += __fdividef(partial, (float)v);
        }
    }

    // warp reduce
#pragma unroll
    for (int off = 16; off > 0; off >>= 1)
        acc += __shfl_xor_sync(0xffffffffu, acc, off);

    __shared__ float warp_sums[8];
    __shared__ bool  is_last;
    const int warp = threadIdx.x >> 5;
    const int lane = threadIdx.x & 31;
    if (lane == 0) warp_sums[warp] = acc;
    __syncthreads();

    if (warp == 0) {
        float bs = (lane < 8) ? warp_sums[lane] : 0.0f;
#pragma unroll
        for (int off = 4; off > 0; off >>= 1)
            bs += __shfl_xor_sync(0xffffffffu, bs, off);
        if (lane == 0) {
            atomicAdd(&g_acc, (double)bs);
            __threadfence();
            const unsigned int done = atomicAdd(&g_count, 1u);
            is_last = (done == gridDim.x - 1);
        }
    }
    __syncthreads();

    if (is_last && threadIdx.x == 0) {
        const double total = g_acc;
        out[0]  = (float)(total / (double)B);
        g_acc   = 0.0;
        __threadfence();
        g_count = 0u;
    }
}

extern "C" void kernel_launch(void* const* d_in, const int* in_sizes, int n_in,
                              void* d_out, int out_size) {
    const float4* yt    = (const float4*)d_in[0];  // y_true  (B, 64) fp32
    const float4* yp    = (const float4*)d_in[1];  // y_pred  (B, 64) fp32
    const float*  param = (const float*)d_in[2];   // (1,)
    const int*    n     = (const int*)d_in[3];     // (B,)
    float* out = (float*)d_out;

    const int B = in_sizes[3];                     // batch
    const int blocks = B / 128;                    // 128 rows per block

    mahal_fused_kernel<<<blocks, 256>>>(yt, yp, param, n, out, B);
}

// round 11
// speedup vs baseline: 1.2605x; 1.2605x over previous
#include <cuda_runtime.h>
#include <cuda_bf16.h>

// Persistent device state; last block resets to 0 so every graph replay
// starts from the same state.
__device__ double       g_acc   = 0.0;
__device__ unsigned int g_count = 0u;

// 16 threads per row, 1 float4 per thread per iteration, 8 iterations.
// Block of 256 threads covers 128 rows. All 8 n-values are loaded up front
// (8 regs) so load predicates are ready at loop entry; data loads for chunks
// entirely beyond n[row] are never issued (exact: masked to zero anyway).
__global__ __launch_bounds__(256) void mahal_fused_kernel(
    const float4* __restrict__ yt,
    const float4* __restrict__ yp,
    const float*  __restrict__ param,
    const int*    __restrict__ n,
    float*        __restrict__ out,
    int B)
{
    const float pm = __ldg(&param[0]);
    const float p  = 2.0f / (1.0f + __expf(-pm)) - 1.0f;
    const float coef2 = -2.0f * p / (1.0f + p * p);   // 2*coef

    const int lin = threadIdx.x & 15;                 // chunk-in-row, constant
    const int t0  = lin * 4;                          // first column of my chunk

    const int blockBase = blockIdx.x * (256 * 8);     // first float4 chunk of block

    // Hoist all n loads: predicates become available before any data load.
    int nv[8];
#pragma unroll
    for (int j = 0; j < 8; j++) {
        const int cid = blockBase + j * 256 + threadIdx.x;
        nv[j] = __ldg(&n[cid >> 4]);
    }

    float acc = 0.0f;

#pragma unroll
    for (int j = 0; j < 8; j++) {
        const int cid = blockBase + j * 256 + threadIdx.x;
        const int v   = nv[j];

        float d0 = 0.0f, d1 = 0.0f, d2 = 0.0f, d3 = 0.0f;
        if (t0 < v) {
            const float4 a = __ldcs(&yt[cid]);
            const float4 b = __ldcs(&yp[cid]);
            d0 = a.x - b.x;                           // t0 < v guaranteed
            d1 = (t0 + 1 < v) ? (a.y - b.y) : 0.0f;
            d2 = (t0 + 2 < v) ? (a.z - b.z) : 0.0f;
            d3 = (t0 + 3 < v) ? (a.w - b.w) : 0.0f;
        }

        float sumsq = d0 * d0;
        sumsq = fmaf(d1, d1, sumsq);
        sumsq = fmaf(d2, d2, sumsq);
        sumsq = fmaf(d3, d3, sumsq);

        float sumadj = d0 * d1;
        sumadj = fmaf(d1, d2, sumadj);
        sumadj = fmaf(d2, d3, sumadj);

        // cross-chunk adjacent product: my d3 * right-neighbor's d0.
        // All lanes execute the shfl; lanes with lin==15 skip the fma.
        const float nd0 = __shfl_down_sync(0xffffffffu, d0, 1);
        if (lin < 15) sumadj = fmaf(d3, nd0, sumadj);

        const float partial = fmaf(coef2, sumadj, sumsq);
        // All 16 lanes of a row share v: divide partials independently.
        acc += __fdividef(partial, (float)v);
    }

    // warp reduce
#pragma unroll
    for (int off = 16; off > 0; off >>= 1)
        acc += __shfl_xor_sync(0xffffffffu, acc, off);

    __shared__ float warp_sums[8];
    __shared__ bool  is_last;
    const int warp = threadIdx.x >> 5;
    const int lane = threadIdx.x & 31;
    if (lane == 0) warp_sums[warp] = acc;
    __syncthreads();

    if (warp == 0) {
        float bs = (lane < 8) ? warp_sums[lane] : 0.0f;
#pragma unroll
        for (int off = 4; off > 0; off >>= 1)
            bs += __shfl_xor_sync(0xffffffffu, bs, off);
        if (lane == 0) {
            atomicAdd(&g_acc, (double)bs);
            __threadfence();
            const unsigned int done = atomicAdd(&g_count, 1u);
            is_last = (done == gridDim.x - 1);
        }
    }
    __syncthreads();

    if (is_last && threadIdx.x == 0) {
        const double total = g_acc;
        out[0]  = (float)(total / (double)B);
        g_acc   = 0.0;
        __threadfence();
        g_count = 0u;
    }
}

extern "C" void kernel_launch(void* const* d_in, const int* in_sizes, int n_in,
                              void* d_out, int out_size) {
    const float4* yt    = (const float4*)d_in[0];  // y_true  (B, 64) fp32
    const float4* yp    = (const float4*)d_in[1];  // y_pred  (B, 64) fp32
    const float*  param = (const float*)d_in[2];   // (1,)
    const int*    n     = (const int*)d_in[3];     // (B,)
    float* out = (float*)d_out;

    const int B = in_sizes[3];                     // batch
    const int blocks = B / 128;                    // 128 rows per block

    mahal_fused_kernel<<<blocks, 256>>>(yt, yp, param, n, out, B);
}